// round 1
// baseline (speedup 1.0000x reference)
#include <cuda_runtime.h>
#include <cuda_bf16.h>

#define HIDDEN 16
#define SPLITS 4
#define MAX_V  65536
#define MAX_B  1024

// Scratch (device globals — no allocation allowed)
__device__ float g_gu[MAX_V * HIDDEN];                 // 4 MB: per-vocab  g*tanh(u)
__device__ float g_partial[SPLITS * MAX_B * HIDDEN];   // partial memory sums

// ---------------------------------------------------------------------------
// Kernel A: per-vocab precompute  gu[v][k] = sigmoid(e_v.Wg+bg) * tanh((e_v.Wu)[k]+bu[k])
// ---------------------------------------------------------------------------
__global__ void precompute_gu(const float* __restrict__ embed,
                              const float* __restrict__ Wg,
                              const float* __restrict__ bg,
                              const float* __restrict__ Wu,
                              const float* __restrict__ bu,
                              int V)
{
    __shared__ float WuS[HIDDEN * HIDDEN];
    __shared__ float WgS[HIDDEN];
    __shared__ float buS[HIDDEN];

    int tid = threadIdx.x;
    for (int i = tid; i < HIDDEN * HIDDEN; i += blockDim.x) WuS[i] = Wu[i];
    if (tid < HIDDEN) { WgS[tid] = Wg[tid]; buS[tid] = bu[tid]; }
    __syncthreads();

    int v = blockIdx.x * blockDim.x + tid;
    if (v >= V) return;

    // load embedding row (64B, aligned)
    float e[HIDDEN];
    const float4* e4 = reinterpret_cast<const float4*>(embed + (size_t)v * HIDDEN);
    #pragma unroll
    for (int j = 0; j < HIDDEN / 4; j++) {
        float4 t = e4[j];
        e[4*j+0] = t.x; e[4*j+1] = t.y; e[4*j+2] = t.z; e[4*j+3] = t.w;
    }

    // gate
    float dg = bg[0];
    #pragma unroll
    for (int h = 0; h < HIDDEN; h++) dg = fmaf(e[h], WgS[h], dg);
    float g = 1.0f / (1.0f + expf(-dg));

    // update + tanh + scale
    float out[HIDDEN];
    #pragma unroll
    for (int k = 0; k < HIDDEN; k++) {
        float a = buS[k];
        #pragma unroll
        for (int h = 0; h < HIDDEN; h++) a = fmaf(e[h], WuS[h * HIDDEN + k], a);
        out[k] = g * tanhf(a);
    }

    float4* gu4 = reinterpret_cast<float4*>(g_gu + (size_t)v * HIDDEN);
    #pragma unroll
    for (int j = 0; j < HIDDEN / 4; j++)
        gu4[j] = make_float4(out[4*j+0], out[4*j+1], out[4*j+2], out[4*j+3]);
}

// ---------------------------------------------------------------------------
// Kernel B: memory_partial[s][b] = sum over a T-chunk of gu[seq[b,t]]
// Block = (s,b). 256 threads: 64 token-groups x 4 float4 lanes.
// ---------------------------------------------------------------------------
__global__ void accumulate_memory(const int* __restrict__ seq, int B, int T)
{
    int b = blockIdx.x % B;
    int s = blockIdx.x / B;
    int tid = threadIdx.x;
    int c   = tid & 3;       // float4 lane within the 16-float row
    int grp = tid >> 2;      // 0..63 token groups

    int chunk  = (T + SPLITS - 1) / SPLITS;
    int tstart = s * chunk;
    int tend   = min(T, tstart + chunk);

    const int* srow = seq + (size_t)b * T;
    const float4* gu4 = reinterpret_cast<const float4*>(g_gu);

    float4 acc = make_float4(0.f, 0.f, 0.f, 0.f);
    #pragma unroll 4
    for (int t = tstart + grp; t < tend; t += 64) {
        int idx = __ldg(&srow[t]);
        float4 r = __ldg(&gu4[(size_t)idx * 4 + c]);
        acc.x += r.x; acc.y += r.y; acc.z += r.z; acc.w += r.w;
    }

    __shared__ float4 red[256];
    red[tid] = acc;
    __syncthreads();
    // reduce over token-groups (stride 4 preserves component c)
    for (int off = 128; off >= 4; off >>= 1) {
        if (tid < off) {
            float4 a = red[tid], o = red[tid + off];
            a.x += o.x; a.y += o.y; a.z += o.z; a.w += o.w;
            red[tid] = a;
        }
        __syncthreads();
    }
    if (tid < 4) {
        float4* p = reinterpret_cast<float4*>(g_partial);
        p[((size_t)s * B + b) * 4 + tid] = red[tid];
    }
}

// ---------------------------------------------------------------------------
// Kernel C: out[b][v] = sum_h memory[b][h] * Wo[h][v] + bo[v]
// Block = (v_tile 256, b_tile 32). FMA-bound by design: Wo tile in regs,
// memory rows read as broadcast LDS.128.
// ---------------------------------------------------------------------------
__global__ void output_gemv(const float* __restrict__ Wo,
                            const float* __restrict__ bo,
                            float* __restrict__ out,
                            int B, int V)
{
    __shared__ float woS[HIDDEN * 256];
    __shared__ float memS[32 * HIDDEN];

    int tid   = threadIdx.x;
    int vtile = blockIdx.x;
    int btile = blockIdx.y;
    int v     = vtile * 256 + tid;
    int b0    = btile * 32;
    bool vok  = (v < V);

    // stage Wo tile
    #pragma unroll
    for (int h = 0; h < HIDDEN; h++)
        woS[h * 256 + tid] = vok ? Wo[(size_t)h * V + v] : 0.0f;

    // stage memory rows for this b-tile (sum the SPLITS partials)
    for (int idx = tid; idx < 32 * HIDDEN; idx += 256) {
        int bl = idx >> 4, h = idx & 15;
        int b = b0 + bl;
        float m = 0.0f;
        if (b < B) {
            #pragma unroll
            for (int s = 0; s < SPLITS; s++)
                m += g_partial[((size_t)s * B + b) * HIDDEN + h];
        }
        memS[idx] = m;
    }
    __syncthreads();

    float wo_r[HIDDEN];
    #pragma unroll
    for (int h = 0; h < HIDDEN; h++) wo_r[h] = woS[h * 256 + tid];

    float bov = vok ? bo[v] : 0.0f;
    int bmax = min(32, B - b0);

    for (int bl = 0; bl < bmax; bl++) {
        const float4* m4 = reinterpret_cast<const float4*>(&memS[bl * HIDDEN]);
        float4 m0 = m4[0], m1 = m4[1], m2 = m4[2], m3 = m4[3];
        float a0 = bov, a1 = 0.0f;
        a0 = fmaf(m0.x, wo_r[0],  a0);  a1 = fmaf(m0.y, wo_r[1],  a1);
        a0 = fmaf(m0.z, wo_r[2],  a0);  a1 = fmaf(m0.w, wo_r[3],  a1);
        a0 = fmaf(m1.x, wo_r[4],  a0);  a1 = fmaf(m1.y, wo_r[5],  a1);
        a0 = fmaf(m1.z, wo_r[6],  a0);  a1 = fmaf(m1.w, wo_r[7],  a1);
        a0 = fmaf(m2.x, wo_r[8],  a0);  a1 = fmaf(m2.y, wo_r[9],  a1);
        a0 = fmaf(m2.z, wo_r[10], a0);  a1 = fmaf(m2.w, wo_r[11], a1);
        a0 = fmaf(m3.x, wo_r[12], a0);  a1 = fmaf(m3.y, wo_r[13], a1);
        a0 = fmaf(m3.z, wo_r[14], a0);  a1 = fmaf(m3.w, wo_r[15], a1);
        if (vok) out[(size_t)(b0 + bl) * V + v] = a0 + a1;
    }
}

// ---------------------------------------------------------------------------
extern "C" void kernel_launch(void* const* d_in, const int* in_sizes, int n_in,
                              void* d_out, int out_size)
{
    const int*   seq   = (const int*)  d_in[0];
    const float* embed = (const float*)d_in[1];
    const float* Wg    = (const float*)d_in[2];
    const float* bg    = (const float*)d_in[3];
    const float* Wu    = (const float*)d_in[4];
    const float* bu    = (const float*)d_in[5];
    const float* Wo    = (const float*)d_in[6];
    const float* bo    = (const float*)d_in[7];
    float*       out   = (float*)d_out;

    int V  = in_sizes[7];              // bo
    int B  = out_size / V;             // out is [B, V]
    int T  = in_sizes[0] / B;          // seq is [B, T]

    // A: per-vocab precompute
    precompute_gu<<<(V + 127) / 128, 128>>>(embed, Wg, bg, Wu, bu, V);

    // B: token gather-accumulate into SPLITS partials
    accumulate_memory<<<SPLITS * B, 256>>>(seq, B, T);

    // C: output projection
    dim3 gridC((V + 255) / 256, (B + 31) / 32);
    output_gemv<<<gridC, 256>>>(Wo, bo, out, B, V);
}